// round 3
// baseline (speedup 1.0000x reference)
#include <cuda_runtime.h>
#include <cuda_bf16.h>

// Problem: Model_69080253989304 — 1-layer tanh RNN, SEQ=4096, BATCH=8192, HID=4.
// Strategy: one thread per batch chain (8192 threads), latency-optimized scalar
// step loop. 128 CTAs x 64 threads -> <=1 CTA per SM, exactly 1 warp per SMSP
// (critical: 2 warps/SMSP would be MUFU-throughput-bound at 2x the period).
// tanh via MUFU.TANH (tanh.approx.f32). x prefetched 16 steps ahead in regs.

#define SEQ    4096
#define BATCH  8192
#define HID    4
#define UNROLL 16

__device__ __forceinline__ float tanh_fast(float x) {
    float r;
    asm("tanh.approx.f32 %0, %1;" : "=f"(r) : "f"(x));
    return r;
}

__global__ void __launch_bounds__(64, 1) rnn_scan_kernel(
    const float* __restrict__ x,      // (SEQ, BATCH, 1)
    const float* __restrict__ h0,     // (1, BATCH, HID)
    const float* __restrict__ W_ih,   // (HID, 1)
    const float* __restrict__ b_ih,   // (HID,)
    const float* __restrict__ W_hh,   // (HID, HID) row-major
    const float* __restrict__ b_hh,   // (HID,)
    const float* __restrict__ fc_W,   // (1, HID)
    const float* __restrict__ fc_b,   // (1,)
    float* __restrict__ out)          // [BATCH] y_last ++ [BATCH*HID] hn
{
    const int b = blockIdx.x * 64 + threadIdx.x;   // grid covers BATCH exactly

    // ---- broadcast weights into registers (L2/L1 broadcast, one-time) ----
    const float w00 = W_hh[0],  w01 = W_hh[1],  w02 = W_hh[2],  w03 = W_hh[3];
    const float w10 = W_hh[4],  w11 = W_hh[5],  w12 = W_hh[6],  w13 = W_hh[7];
    const float w20 = W_hh[8],  w21 = W_hh[9],  w22 = W_hh[10], w23 = W_hh[11];
    const float w30 = W_hh[12], w31 = W_hh[13], w32 = W_hh[14], w33 = W_hh[15];

    const float wi0 = W_ih[0], wi1 = W_ih[1], wi2 = W_ih[2], wi3 = W_ih[3];
    // fold b_ih + b_hh into a single per-component bias
    const float c0b = b_ih[0] + b_hh[0];
    const float c1b = b_ih[1] + b_hh[1];
    const float c2b = b_ih[2] + b_hh[2];
    const float c3b = b_ih[3] + b_hh[3];

    // ---- initial hidden state (vectorized: HID=4 -> one float4 per batch) ----
    const float4 hi = reinterpret_cast<const float4*>(h0)[b];
    float hv0 = hi.x, hv1 = hi.y, hv2 = hi.z, hv3 = hi.w;

    const float* xp = x + b;   // per-step stride = BATCH floats (coalesced over lanes)

    // ---- software-pipelined register double buffer for x ----
    float xs[UNROLL];
#pragma unroll
    for (int i = 0; i < UNROLL; i++) xs[i] = xp[i * BATCH];

    for (int t0 = 0; t0 < SEQ; t0 += UNROLL) {
        // prefetch next block while computing this one
        float xn[UNROLL];
        const int tn = t0 + UNROLL;
        if (tn < SEQ) {
#pragma unroll
            for (int i = 0; i < UNROLL; i++) xn[i] = xp[(tn + i) * BATCH];
        } else {
#pragma unroll
            for (int i = 0; i < UNROLL; i++) xn[i] = 0.0f;
        }

#pragma unroll
        for (int i = 0; i < UNROLL; i++) {
            const float xv = xs[i];
            // input projection + fused bias (off the critical chain)
            const float c0 = fmaf(wi0, xv, c0b);
            const float c1 = fmaf(wi1, xv, c1b);
            const float c2 = fmaf(wi2, xv, c2b);
            const float c3 = fmaf(wi3, xv, c3b);
            // dot products: consume h components in MUFU arrival order (h0 first)
            const float s0 = fmaf(w03, hv3, fmaf(w02, hv2, fmaf(w01, hv1, fmaf(w00, hv0, c0))));
            const float s1 = fmaf(w13, hv3, fmaf(w12, hv2, fmaf(w11, hv1, fmaf(w10, hv0, c1))));
            const float s2 = fmaf(w23, hv3, fmaf(w22, hv2, fmaf(w21, hv1, fmaf(w20, hv0, c2))));
            const float s3 = fmaf(w33, hv3, fmaf(w32, hv2, fmaf(w31, hv1, fmaf(w30, hv0, c3))));
            hv0 = tanh_fast(s0);
            hv1 = tanh_fast(s1);
            hv2 = tanh_fast(s2);
            hv3 = tanh_fast(s3);
        }

#pragma unroll
        for (int i = 0; i < UNROLL; i++) xs[i] = xn[i];
    }

    // ---- epilogue: y = fc(h_T), write y_last then hn ----
    const float y = fmaf(fc_W[3], hv3,
                    fmaf(fc_W[2], hv2,
                    fmaf(fc_W[1], hv1,
                    fmaf(fc_W[0], hv0, fc_b[0]))));

    out[b] = y;                                         // y_last: (BATCH, 1)
    float4 hvec;
    hvec.x = hv0; hvec.y = hv1; hvec.z = hv2; hvec.w = hv3;
    reinterpret_cast<float4*>(out + BATCH)[b] = hvec;   // hn: (1, BATCH, HID)
}

extern "C" void kernel_launch(void* const* d_in, const int* in_sizes, int n_in,
                              void* d_out, int out_size) {
    const float* x    = (const float*)d_in[0];
    const float* h0   = (const float*)d_in[1];
    const float* W_ih = (const float*)d_in[2];
    const float* b_ih = (const float*)d_in[3];
    const float* W_hh = (const float*)d_in[4];
    const float* b_hh = (const float*)d_in[5];
    const float* fc_W = (const float*)d_in[6];
    const float* fc_b = (const float*)d_in[7];
    float* out = (float*)d_out;

    rnn_scan_kernel<<<BATCH / 64, 64>>>(x, h0, W_ih, b_ih, W_hh, b_hh,
                                        fc_W, fc_b, out);
}

// round 5
// speedup vs baseline: 1.1656x; 1.1656x over previous
#include <cuda_runtime.h>
#include <cuda_bf16.h>

// Model_69080253989304 — 1-layer tanh RNN, SEQ=4096, BATCH=8192, HID=4.
// R3: eliminate register spills (R2 had ~75 live regs capped at 64 -> LDL/STL
// in the serial loop). x is now staged through a per-thread-private smem
// double buffer filled with cp.async (zero register cost). No __syncthreads
// needed: thread tid writes and reads only smem column tid.
// One thread per batch chain; 128 CTAs x 64 thr -> 1 warp/SMSP on 128 SMs.

#define SEQ    4096
#define BATCH  8192
#define CHUNK  32
#define NCHUNK (SEQ / CHUNK)

__device__ __forceinline__ float tanh_fast(float x) {
    float r;
    asm("tanh.approx.f32 %0, %1;" : "=f"(r) : "f"(x));
    return r;
}

__global__ void __launch_bounds__(64, 1) rnn_scan_kernel(
    const float* __restrict__ x,      // (SEQ, BATCH, 1)
    const float* __restrict__ h0,     // (1, BATCH, HID)
    const float* __restrict__ W_ih,   // (HID, 1)
    const float* __restrict__ b_ih,   // (HID,)
    const float* __restrict__ W_hh,   // (HID, HID) row-major
    const float* __restrict__ b_hh,   // (HID,)
    const float* __restrict__ fc_W,   // (1, HID)
    const float* __restrict__ fc_b,   // (1,)
    float* __restrict__ out)          // [BATCH] y_last ++ [BATCH*HID] hn
{
    __shared__ float xb[2][CHUNK * 64];   // 16 KB, per-thread-private columns

    const int tid = threadIdx.x;
    const int b   = blockIdx.x * 64 + tid;

    // ---- broadcast weights into registers ----
    const float w00 = W_hh[0],  w01 = W_hh[1],  w02 = W_hh[2],  w03 = W_hh[3];
    const float w10 = W_hh[4],  w11 = W_hh[5],  w12 = W_hh[6],  w13 = W_hh[7];
    const float w20 = W_hh[8],  w21 = W_hh[9],  w22 = W_hh[10], w23 = W_hh[11];
    const float w30 = W_hh[12], w31 = W_hh[13], w32 = W_hh[14], w33 = W_hh[15];

    const float wi0 = W_ih[0], wi1 = W_ih[1], wi2 = W_ih[2], wi3 = W_ih[3];
    const float c0b = b_ih[0] + b_hh[0];
    const float c1b = b_ih[1] + b_hh[1];
    const float c2b = b_ih[2] + b_hh[2];
    const float c3b = b_ih[3] + b_hh[3];

    // ---- prologue: prefetch chunk 0 into buffer 0 via cp.async ----
    {
        const float* src = x + b;
        unsigned dst = (unsigned)__cvta_generic_to_shared(&xb[0][tid]);
#pragma unroll
        for (int i = 0; i < CHUNK; ++i) {
            asm volatile("cp.async.ca.shared.global [%0], [%1], 4;"
                         :: "r"(dst + i * 64 * 4), "l"(src + (size_t)i * BATCH)
                         : "memory");
        }
        asm volatile("cp.async.commit_group;" ::: "memory");
    }

    // ---- initial hidden state ----
    const float4 hi = reinterpret_cast<const float4*>(h0)[b];
    float hv0 = hi.x, hv1 = hi.y, hv2 = hi.z, hv3 = hi.w;

    for (int n = 0; n < NCHUNK; ++n) {
        // chunk n's loads are the only outstanding group -> wait for them
        asm volatile("cp.async.wait_group 0;" ::: "memory");

        const int cur = n & 1;
        // prefetch source for chunk n+1 (clamped to chunk 0 on the last
        // iteration: harmless redundant load into the dead buffer)
        const int nrow = (n + 1 < NCHUNK) ? (n + 1) * CHUNK : 0;
        const float* psrc = x + (size_t)nrow * BATCH + b;
        unsigned pdst = (unsigned)__cvta_generic_to_shared(&xb[cur ^ 1][tid]);
        const float* xcur = &xb[cur][tid];

#pragma unroll
        for (int i = 0; i < CHUNK; ++i) {
            // one prefetch per step: spreads LDGSTS issue across the chunk
            asm volatile("cp.async.ca.shared.global [%0], [%1], 4;"
                         :: "r"(pdst + i * 64 * 4), "l"(psrc + (size_t)i * BATCH)
                         : "memory");

            const float xv = xcur[i * 64];
            // input projection + fused bias (off the critical chain)
            const float c0 = fmaf(wi0, xv, c0b);
            const float c1 = fmaf(wi1, xv, c1b);
            const float c2 = fmaf(wi2, xv, c2b);
            const float c3 = fmaf(wi3, xv, c3b);
            // dot products consume h components in MUFU arrival order
            const float s0 = fmaf(w03, hv3, fmaf(w02, hv2, fmaf(w01, hv1, fmaf(w00, hv0, c0))));
            const float s1 = fmaf(w13, hv3, fmaf(w12, hv2, fmaf(w11, hv1, fmaf(w10, hv0, c1))));
            const float s2 = fmaf(w23, hv3, fmaf(w22, hv2, fmaf(w21, hv1, fmaf(w20, hv0, c2))));
            const float s3 = fmaf(w33, hv3, fmaf(w32, hv2, fmaf(w31, hv1, fmaf(w30, hv0, c3))));
            hv0 = tanh_fast(s0);
            hv1 = tanh_fast(s1);
            hv2 = tanh_fast(s2);
            hv3 = tanh_fast(s3);
        }
        asm volatile("cp.async.commit_group;" ::: "memory");
    }

    // ---- epilogue: y = fc(h_T) ----
    const float y = fmaf(fc_W[3], hv3,
                    fmaf(fc_W[2], hv2,
                    fmaf(fc_W[1], hv1,
                    fmaf(fc_W[0], hv0, fc_b[0]))));

    out[b] = y;                                         // y_last: (BATCH, 1)
    float4 hvec;
    hvec.x = hv0; hvec.y = hv1; hvec.z = hv2; hvec.w = hv3;
    reinterpret_cast<float4*>(out + BATCH)[b] = hvec;   // hn: (1, BATCH, HID)
}

extern "C" void kernel_launch(void* const* d_in, const int* in_sizes, int n_in,
                              void* d_out, int out_size) {
    const float* x    = (const float*)d_in[0];
    const float* h0   = (const float*)d_in[1];
    const float* W_ih = (const float*)d_in[2];
    const float* b_ih = (const float*)d_in[3];
    const float* W_hh = (const float*)d_in[4];
    const float* b_hh = (const float*)d_in[5];
    const float* fc_W = (const float*)d_in[6];
    const float* fc_b = (const float*)d_in[7];
    float* out = (float*)d_out;

    rnn_scan_kernel<<<BATCH / 64, 64>>>(x, h0, W_ih, b_ih, W_hh, b_hh,
                                        fc_W, fc_b, out);
}